// round 6
// baseline (speedup 1.0000x reference)
#include <cuda_runtime.h>
#include <math.h>

// ---------------------------------------------------------------------------
// NoisyTopkRouter: B=128, T1=128, T2=8, D=1024, E=64
// Two kernels (deterministic, no cross-block sync):
//  1) pool_kernel: mean-pool 512MB stream -> per-(b,ts) partials  (HBM-bound)
//  2) router_kernel: 64 blocks x 2 batches each. Halves W L2 traffic vs
//     1-batch-per-block (32MB vs 64MB) and doubles W-load reuse.
// Outputs: router_output [B,E] then noisy [B,E].
// ---------------------------------------------------------------------------

#define B_ 128
#define TT 1024   // T1*T2
#define D_ 1024
#define E_ 64
#define TSPLIT 8
#define TCHUNK (TT / TSPLIT)  // 128

// partials: [B][TSPLIT][256] float4 = 4 MiB
__device__ float4 g_partial[B_ * TSPLIT * 256];

__global__ void __launch_bounds__(256) pool_kernel(const float* __restrict__ mh) {
    const int b   = blockIdx.x;
    const int ts  = blockIdx.y;
    const int tid = threadIdx.x;

    const float4* p = reinterpret_cast<const float4*>(
        mh + ((size_t)b * TT + (size_t)ts * TCHUNK) * D_) + tid;

    float4 acc = make_float4(0.f, 0.f, 0.f, 0.f);
#pragma unroll 8
    for (int t = 0; t < TCHUNK; ++t) {
        float4 v = __ldcs(p + (size_t)t * (D_ / 4));  // streaming: no reuse
        acc.x += v.x; acc.y += v.y; acc.z += v.z; acc.w += v.w;
    }
    g_partial[(b * TSPLIT + ts) * 256 + tid] = acc;
}

__device__ __forceinline__ float softplus_f(float x) {
    // jax.nn.softplus = logaddexp(x, 0)
    return fmaxf(x, 0.f) + log1pf(expf(-fabsf(x)));
}

// 64 blocks, 2 batches per block. 256 threads.
__global__ void __launch_bounds__(256) router_kernel(
    const float* __restrict__ b_route, const float* __restrict__ W_route,
    const float* __restrict__ W_noise, const float* __restrict__ b_noise,
    const float* __restrict__ noise_eps, const int* __restrict__ mis_mask,
    float* __restrict__ out, int out_size)
{
    __shared__ __align__(16) float pooled2[2][D_];
    __shared__ float lraw[2][E_], nraw[2][E_];
    __shared__ float ebuf1[2][E_], ebuf2[2][E_];
    __shared__ float noisy_s[2][E_], sparse_s[2][E_];

    const int b0  = blockIdx.x * 2;
    const int tid = threadIdx.x;

    // --- finish pooling for both batches: sum 8 partials, divide by TT ---
    {
        const float inv = 1.0f / (float)TT;
#pragma unroll
        for (int bi = 0; bi < 2; ++bi) {
            float4 acc = make_float4(0.f, 0.f, 0.f, 0.f);
#pragma unroll
            for (int t = 0; t < TSPLIT; ++t) {
                float4 v = g_partial[((b0 + bi) * TSPLIT + t) * 256 + tid];
                acc.x += v.x; acc.y += v.y; acc.z += v.z; acc.w += v.w;
            }
            reinterpret_cast<float4*>(pooled2[bi])[tid] =
                make_float4(acc.x * inv, acc.y * inv, acc.z * inv, acc.w * inv);
        }
    }
    __syncthreads();

    // --- dual GEMV, W reused across 2 batches: warp w -> experts [8w, 8w+8) ---
    {
        const int w = tid >> 5, lane = tid & 31;
        const float4* p0 = reinterpret_cast<const float4*>(pooled2[0]);
        const float4* p1 = reinterpret_cast<const float4*>(pooled2[1]);
#pragma unroll
        for (int ei = 0; ei < 8; ++ei) {
            const int e = w * 8 + ei;
            const float4* wr = reinterpret_cast<const float4*>(W_route) + (size_t)e * (D_ / 4);
            const float4* wn = reinterpret_cast<const float4*>(W_noise) + (size_t)e * (D_ / 4);
            float ar0 = 0.f, an0 = 0.f, ar1 = 0.f, an1 = 0.f;
#pragma unroll
            for (int j = lane; j < D_ / 4; j += 32) {
                float4 a  = __ldg(wr + j);
                float4 c  = __ldg(wn + j);
                float4 v0 = p0[j];
                float4 v1 = p1[j];
                ar0 += v0.x * a.x + v0.y * a.y + v0.z * a.z + v0.w * a.w;
                an0 += v0.x * c.x + v0.y * c.y + v0.z * c.z + v0.w * c.w;
                ar1 += v1.x * a.x + v1.y * a.y + v1.z * a.z + v1.w * a.w;
                an1 += v1.x * c.x + v1.y * c.y + v1.z * c.z + v1.w * c.w;
            }
#pragma unroll
            for (int o = 16; o; o >>= 1) {
                ar0 += __shfl_xor_sync(0xffffffffu, ar0, o);
                an0 += __shfl_xor_sync(0xffffffffu, an0, o);
                ar1 += __shfl_xor_sync(0xffffffffu, ar1, o);
                an1 += __shfl_xor_sync(0xffffffffu, an1, o);
            }
            if (lane == 0) {
                lraw[0][e] = ar0 + b_route[e];
                nraw[0][e] = an0 + b_noise[e];
                lraw[1][e] = ar1 + b_route[e];
                nraw[1][e] = an1 + b_noise[e];
            }
        }
    }
    __syncthreads();

    // --- scalar chain: threads 0..127 active; bi = tid>>6, e = tid&63 ---
    const int bi = tid >> 6;
    const int e  = tid & 63;
    const int b  = b0 + bi;
    const int active = (tid < 2 * E_);
    float logit = 0.f;

    if (active) {
        float m1 = -INFINITY;
#pragma unroll
        for (int j = 0; j < E_; ++j) m1 = fmaxf(m1, lraw[bi][j]);
        ebuf1[bi][e] = expf(lraw[bi][e] - m1);
        nraw[bi][e] = noise_eps[b * E_ + e] * softplus_f(nraw[bi][e]);
    }
    __syncthreads();

    if (active) {
        float s1 = 0.f;
#pragma unroll
        for (int j = 0; j < E_; ++j) s1 += ebuf1[bi][j];
        logit = ebuf1[bi][e] / s1;

        float m2 = -INFINITY;
#pragma unroll
        for (int j = 0; j < E_; ++j) m2 = fmaxf(m2, nraw[bi][j]);
        ebuf2[bi][e] = expf(nraw[bi][e] - m2);
    }
    __syncthreads();

    if (active) {
        float s2 = 0.f;
#pragma unroll
        for (int j = 0; j < E_; ++j) s2 += ebuf2[bi][j];
        float noisy = logit + ebuf2[bi][e] / s2;
        noisy_s[bi][e] = noisy;
        if (out_size >= 2 * B_ * E_)
            out[B_ * E_ + b * E_ + e] = noisy;     // second output: noisy
    }
    __syncthreads();

    if (active) {
        // stable descending rank (ties -> lower index first)
        const float myv = noisy_s[bi][e];
        int rank = 0;
#pragma unroll
        for (int j = 0; j < E_; ++j) {
            float vj = noisy_s[bi][j];
            rank += (vj > myv) || (vj == myv && j < e);
        }
        const int k = mis_mask[b];
        float sp = (rank < k) ? myv : 0.f;
        if (k < E_ && e == 0) sp = 0.f;   // torch pad-scatter quirk
        sparse_s[bi][e] = sp;
    }
    __syncthreads();

    if (active) {
        float m3 = -INFINITY;
#pragma unroll
        for (int j = 0; j < E_; ++j) m3 = fmaxf(m3, sparse_s[bi][j]);
        ebuf1[bi][e] = expf(sparse_s[bi][e] - m3);
    }
    __syncthreads();

    if (active) {
        float s3 = 0.f;
#pragma unroll
        for (int j = 0; j < E_; ++j) s3 += ebuf1[bi][j];
        out[b * E_ + e] = ebuf1[bi][e] / s3;       // first output: router_output
    }
}

extern "C" void kernel_launch(void* const* d_in, const int* in_sizes, int n_in,
                              void* d_out, int out_size) {
    const float* mh        = (const float*)d_in[0];
    const float* W_route   = (const float*)d_in[1];
    const float* b_route   = (const float*)d_in[2];
    const float* W_noise   = (const float*)d_in[3];
    const float* b_noise   = (const float*)d_in[4];
    const float* noise_eps = (const float*)d_in[5];
    const int*   mis_mask  = (const int*)d_in[6];
    float* out = (float*)d_out;

    dim3 g1(B_, TSPLIT);
    pool_kernel<<<g1, 256>>>(mh);
    router_kernel<<<B_ / 2, 256>>>(b_route, W_route, W_noise, b_noise,
                                   noise_eps, mis_mask, out, out_size);
}

// round 7
// speedup vs baseline: 1.0929x; 1.0929x over previous
#include <cuda_runtime.h>
#include <math.h>

// ---------------------------------------------------------------------------
// NoisyTopkRouter: B=128, T1=128, T2=8, D=1024, E=64
// Two kernels (deterministic):
//  1) pool_kernel: mean-pool 512MB stream -> per-(b,ts) partials (HBM-bound,
//     proven R2 config: 1024 blocks x 256 thr, unroll-8 float4 __ldcs)
//  2) router_kernel: 64 blocks x 1024 threads, 2 batches per block.
//     High warp count (latency-bound fix from R6) + W reuse across
//     2 batches x 2 matrices per load (traffic fix: 32MB L2).
// Outputs: router_output [B,E] then noisy [B,E].
// ---------------------------------------------------------------------------

#define B_ 128
#define TT 1024   // T1*T2
#define D_ 1024
#define E_ 64
#define TSPLIT 8
#define TCHUNK (TT / TSPLIT)  // 128

// partials: [B][TSPLIT][256] float4 = 4 MiB
__device__ float4 g_partial[B_ * TSPLIT * 256];

__global__ void __launch_bounds__(256) pool_kernel(const float* __restrict__ mh) {
    const int b   = blockIdx.x;
    const int ts  = blockIdx.y;
    const int tid = threadIdx.x;

    const float4* p = reinterpret_cast<const float4*>(
        mh + ((size_t)b * TT + (size_t)ts * TCHUNK) * D_) + tid;

    float4 acc = make_float4(0.f, 0.f, 0.f, 0.f);
#pragma unroll 8
    for (int t = 0; t < TCHUNK; ++t) {
        float4 v = __ldcs(p + (size_t)t * (D_ / 4));  // streaming: no reuse
        acc.x += v.x; acc.y += v.y; acc.z += v.z; acc.w += v.w;
    }
    g_partial[(b * TSPLIT + ts) * 256 + tid] = acc;
}

__device__ __forceinline__ float softplus_f(float x) {
    // jax.nn.softplus = logaddexp(x, 0)
    return fmaxf(x, 0.f) + log1pf(expf(-fabsf(x)));
}

// 64 blocks x 1024 threads; block handles batches (2*bx, 2*bx+1).
// Warp w: experts w and w+32, both matrices, both batches.
__global__ void __launch_bounds__(1024) router_kernel(
    const float* __restrict__ W_route, const float* __restrict__ b_route,
    const float* __restrict__ W_noise, const float* __restrict__ b_noise,
    const float* __restrict__ noise_eps, const int* __restrict__ mis_mask,
    float* __restrict__ out, int out_size)
{
    __shared__ __align__(16) float pooled2[2][D_];
    __shared__ float lraw[2][E_], nraw[2][E_];
    __shared__ float ebuf1[2][E_], ebuf2[2][E_];
    __shared__ float noisy_s[2][E_], sparse_s[2][E_];

    const int b0  = blockIdx.x * 2;
    const int tid = threadIdx.x;

    // --- finish pooling for both batches: thread owns d=tid, sums 8 partials ---
    {
        const float* gp = reinterpret_cast<const float*>(g_partial);
        const float inv = 1.0f / (float)TT;
#pragma unroll
        for (int bi = 0; bi < 2; ++bi) {
            float acc = 0.f;
#pragma unroll
            for (int t = 0; t < TSPLIT; ++t)
                acc += gp[((size_t)((b0 + bi) * TSPLIT + t)) * 1024 + tid];
            pooled2[bi][tid] = acc * inv;
        }
    }
    __syncthreads();

    // --- dual GEMV: warp w -> experts w and w+32; float4 over D;
    //     each W load reused for 2 batches ---
    {
        const int w = tid >> 5, lane = tid & 31;
        const float4* p0 = reinterpret_cast<const float4*>(pooled2[0]);
        const float4* p1 = reinterpret_cast<const float4*>(pooled2[1]);
#pragma unroll
        for (int ei = 0; ei < 2; ++ei) {
            const int e = w + ei * 32;
            const float4* wr = reinterpret_cast<const float4*>(W_route) + (size_t)e * (D_ / 4);
            const float4* wn = reinterpret_cast<const float4*>(W_noise) + (size_t)e * (D_ / 4);
            float ar0 = 0.f, an0 = 0.f, ar1 = 0.f, an1 = 0.f;
#pragma unroll
            for (int j = lane; j < D_ / 4; j += 32) {
                float4 a  = __ldg(wr + j);
                float4 c  = __ldg(wn + j);
                float4 v0 = p0[j];
                float4 v1 = p1[j];
                ar0 += v0.x * a.x + v0.y * a.y + v0.z * a.z + v0.w * a.w;
                an0 += v0.x * c.x + v0.y * c.y + v0.z * c.z + v0.w * c.w;
                ar1 += v1.x * a.x + v1.y * a.y + v1.z * a.z + v1.w * a.w;
                an1 += v1.x * c.x + v1.y * c.y + v1.z * c.z + v1.w * c.w;
            }
#pragma unroll
            for (int o = 16; o; o >>= 1) {
                ar0 += __shfl_xor_sync(0xffffffffu, ar0, o);
                an0 += __shfl_xor_sync(0xffffffffu, an0, o);
                ar1 += __shfl_xor_sync(0xffffffffu, ar1, o);
                an1 += __shfl_xor_sync(0xffffffffu, an1, o);
            }
            if (lane == 0) {
                lraw[0][e] = ar0 + b_route[e];
                nraw[0][e] = an0 + b_noise[e];
                lraw[1][e] = ar1 + b_route[e];
                nraw[1][e] = an1 + b_noise[e];
            }
        }
    }
    __syncthreads();

    // --- scalar chain: threads 0..127 active; bi = tid>>6, e = tid&63 ---
    const int bi = tid >> 6;
    const int e  = tid & 63;
    const int b  = b0 + bi;
    const int active = (tid < 2 * E_);
    float logit = 0.f;

    if (active) {
        float m1 = -INFINITY;
#pragma unroll
        for (int j = 0; j < E_; ++j) m1 = fmaxf(m1, lraw[bi][j]);
        ebuf1[bi][e] = expf(lraw[bi][e] - m1);
        nraw[bi][e] = noise_eps[b * E_ + e] * softplus_f(nraw[bi][e]);
    }
    __syncthreads();

    if (active) {
        float s1 = 0.f;
#pragma unroll
        for (int j = 0; j < E_; ++j) s1 += ebuf1[bi][j];
        logit = ebuf1[bi][e] / s1;

        float m2 = -INFINITY;
#pragma unroll
        for (int j = 0; j < E_; ++j) m2 = fmaxf(m2, nraw[bi][j]);
        ebuf2[bi][e] = expf(nraw[bi][e] - m2);
    }
    __syncthreads();

    if (active) {
        float s2 = 0.f;
#pragma unroll
        for (int j = 0; j < E_; ++j) s2 += ebuf2[bi][j];
        float noisy = logit + ebuf2[bi][e] / s2;
        noisy_s[bi][e] = noisy;
        if (out_size >= 2 * B_ * E_)
            out[B_ * E_ + b * E_ + e] = noisy;     // second output: noisy
    }
    __syncthreads();

    if (active) {
        // stable descending rank (ties -> lower index first)
        const float myv = noisy_s[bi][e];
        int rank = 0;
#pragma unroll
        for (int j = 0; j < E_; ++j) {
            float vj = noisy_s[bi][j];
            rank += (vj > myv) || (vj == myv && j < e);
        }
        const int k = mis_mask[b];
        float sp = (rank < k) ? myv : 0.f;
        if (k < E_ && e == 0) sp = 0.f;   // torch pad-scatter quirk
        sparse_s[bi][e] = sp;
    }
    __syncthreads();

    if (active) {
        float m3 = -INFINITY;
#pragma unroll
        for (int j = 0; j < E_; ++j) m3 = fmaxf(m3, sparse_s[bi][j]);
        ebuf1[bi][e] = expf(sparse_s[bi][e] - m3);
    }
    __syncthreads();

    if (active) {
        float s3 = 0.f;
#pragma unroll
        for (int j = 0; j < E_; ++j) s3 += ebuf1[bi][j];
        out[b * E_ + e] = ebuf1[bi][e] / s3;       // first output: router_output
    }
}

extern "C" void kernel_launch(void* const* d_in, const int* in_sizes, int n_in,
                              void* d_out, int out_size) {
    const float* mh        = (const float*)d_in[0];
    const float* W_route   = (const float*)d_in[1];
    const float* b_route   = (const float*)d_in[2];
    const float* W_noise   = (const float*)d_in[3];
    const float* b_noise   = (const float*)d_in[4];
    const float* noise_eps = (const float*)d_in[5];
    const int*   mis_mask  = (const int*)d_in[6];
    float* out = (float*)d_out;

    dim3 g1(B_, TSPLIT);
    pool_kernel<<<g1, 256>>>(mh);
    router_kernel<<<B_ / 2, 1024>>>(W_route, b_route, W_noise, b_noise,
                                    noise_eps, mis_mask, out, out_size);
}